// round 15
// baseline (speedup 1.0000x reference)
#include <cuda_runtime.h>
#include <math.h>

// Fixed shapes per reference
#define HH    112
#define WW    112
#define AA    9
#define NBOX  768          // B * 24
#define NCELL 3612672      // B*H*W*A

#define TILE_B   10240     // bytes per bulk-copy tile (2560 floats, mult of 5)
#define NTILES   7056      // 72,253,440 / 10,240
#define BLOCKS   1216      // 8 CTAs x 152 SMs (GB300 has 152, not 148)
#define THREADS  256
#define PREP_BLOCK 1215    // in the 5-tile group: has slack for box prep

__device__ float g_partials[BLOCKS];
__device__ int   g_counter = 0;   // zero-inited; last block resets it
__device__ float g_box3[3];       // coord, objs, sppos (written by PREP_BLOCK)
__device__ int   g_npos;

__device__ __forceinline__ float softplus_acc(float x) {
    return fmaxf(x, 0.0f) + log1pf(expf(-fabsf(x)));
}

__device__ __forceinline__ unsigned smem_u32(const void* p) {
    return (unsigned)__cvta_generic_to_shared(p);
}

#define MBAR_INIT(a, c) \
    asm volatile("mbarrier.init.shared.b64 [%0], %1;" :: "r"(a), "r"(c) : "memory")
#define MBAR_EXPECT(a, b) \
    asm volatile("mbarrier.arrive.expect_tx.shared.b64 _, [%0], %1;" :: "r"(a), "r"(b) : "memory")
#define BULK_G2S_EL(dst, src, n, mb, pol) \
    asm volatile("cp.async.bulk.shared::cta.global.mbarrier::complete_tx::bytes.L2::cache_hint [%0], [%1], %2, [%3], %4;" \
                 :: "r"(dst), "l"(src), "r"(n), "r"(mb), "l"(pol) : "memory")
#define WAITP(mb, ph) do { \
    asm volatile("{\n\t.reg .pred P;\n" \
                 "W%=:\n\tmbarrier.try_wait.parity.acquire.cta.shared::cta.b64 P, [%0], %1;\n" \
                 "\t@P bra D%=;\n\tbra W%=;\nD%=:\n\t}" \
                 :: "r"(mb), "r"(ph) : "memory"); \
} while (0)

__global__ __launch_bounds__(THREADS, 8) void loss_kernel(const float* __restrict__ pred,
                                                          const float* __restrict__ bbox,
                                                          float* __restrict__ out) {
    __shared__ __align__(128) unsigned char smem_raw[2 * TILE_B];
    __shared__ __align__(8) unsigned long long mbar[2];
    __shared__ float s_red[THREADS];
    __shared__ int   s_key[NBOX];     // used only by PREP_BLOCK
    __shared__ bool  is_last;

    const int tid = threadIdx.x;
    const unsigned sb  = smem_u32(smem_raw);
    const unsigned mb0 = smem_u32(&mbar[0]);
    const unsigned mb1 = smem_u32(&mbar[1]);
    const char* __restrict__ pb = reinterpret_cast<const char*>(pred);

    unsigned long long pol;
    asm volatile("createpolicy.fractional.L2::evict_last.b64 %0, 1.0;" : "=l"(pol));

    if (tid == 0) { MBAR_INIT(mb0, 1); MBAR_INIT(mb1, 1); }
    __syncthreads();

    // Kick off the first two bulk copies immediately (overlap with prep below).
    {
        long long t0 = blockIdx.x;
        long long t1 = blockIdx.x + (long long)BLOCKS;
        if (tid == 0) {
            if (t0 < NTILES) {
                MBAR_EXPECT(mb0, TILE_B);
                BULK_G2S_EL(sb, pb + t0 * TILE_B, TILE_B, mb0, pol);
            }
            if (t1 < NTILES) {
                MBAR_EXPECT(mb1, TILE_B);
                BULK_G2S_EL(sb + TILE_B, pb + t1 * TILE_B, TILE_B, mb1, pol);
            }
        }
    }

    // ---------- Box prep: PREP_BLOCK only, overlapped with its streaming slack ----------
    if (blockIdx.x == PREP_BLOCK) {
        float aw[AA], ah[AA];
        {
            const double S[3] = {32.0, 64.0, 128.0};
            const double R[3] = {0.5, 1.0, 2.0};
            #pragma unroll
            for (int i = 0; i < AA; i++) {
                double sd = S[i / 3], rd = R[i % 3];
                aw[i] = (float)(sd * sqrt(rd) / 224.0);
                ah[i] = (float)(sd / sqrt(rd) / 224.0);
            }
        }

        float tgt[3][4];
        #pragma unroll
        for (int k = 0; k < 3; k++) {
            int idx = tid + k * THREADS;
            float cx = bbox[idx * 4 + 0];
            float cy = bbox[idx * 4 + 1];
            float w  = bbox[idx * 4 + 2];
            float h  = bbox[idx * 4 + 3];
            bool valid = (cx != 0.0f) || (cy != 0.0f) || (w != 0.0f) || (h != 0.0f);
            if (!valid) { s_key[idx] = -1; tgt[k][0]=tgt[k][1]=tgt[k][2]=tgt[k][3]=0.0f; continue; }

            int gx = (int)floorf(cx * (float)WW); gx = min(max(gx, 0), WW - 1);
            int gy = (int)floorf(cy * (float)HH); gy = min(max(gy, 0), HH - 1);

            float wh = w * h;
            int best = 0; float bi = -1e30f;
            #pragma unroll
            for (int a = 0; a < AA; a++) {
                float inter = fminf(w, aw[a]) * fminf(h, ah[a]);
                float uni   = wh + aw[a] * ah[a] - inter;
                float iou   = inter / (uni + 1e-16f);
                if (iou > bi) { bi = iou; best = a; }   // first max wins (strict >)
            }

            int b = idx / 24;
            s_key[idx] = ((b * HH + gy) * WW + gx) * AA + best;
            tgt[k][0] = cx * (float)WW - (float)gx;
            tgt[k][1] = cy * (float)HH - (float)gy;
            tgt[k][2] = logf(w / aw[best] + 1e-16f);
            tgt[k][3] = logf(h / ah[best] + 1e-16f);
        }
        __syncthreads();

        float coord = 0.0f, objs = 0.0f, sppos = 0.0f;
        int npos = 0;
        #pragma unroll
        for (int k = 0; k < 3; k++) {
            int idx = tid + k * THREADS;
            int key = s_key[idx];
            if (key < 0) continue;
            int bend = ((idx / 24) + 1) * 24;
            bool win = true;
            for (int j = idx + 1; j < bend; j++) {
                if (s_key[j] == key) { win = false; break; }
            }
            if (!win) continue;

            const float* p = pred + (long long)key * 5;
            float d0 = p[0] - tgt[k][0];
            float d1 = p[1] - tgt[k][1];
            float d2 = p[2] - tgt[k][2];
            float d3 = p[3] - tgt[k][3];
            coord += d0 * d0 + d1 * d1 + d2 * d2 + d3 * d3;
            float o = p[4];
            objs  += softplus_acc(-o);
            sppos += softplus_acc(o);
            npos++;
        }

        float vals[3] = {coord, objs, sppos};
        #pragma unroll
        for (int v = 0; v < 3; v++) {
            s_red[tid] = vals[v];
            __syncthreads();
            #pragma unroll
            for (int o = THREADS / 2; o > 0; o >>= 1) {
                if (tid < o) s_red[tid] += s_red[tid + o];
                __syncthreads();
            }
            if (tid == 0) g_box3[v] = s_red[0];
            __syncthreads();
        }
        s_red[tid] = (float)npos;
        __syncthreads();
        #pragma unroll
        for (int o = THREADS / 2; o > 0; o >>= 1) {
            if (tid < o) s_red[tid] += s_red[tid + o];
            __syncthreads();
        }
        if (tid == 0) g_npos = (int)s_red[0];
        __syncthreads();
    }

    // ---------- Phase 1: bulk-copy pipeline, sum softplus over obj channel ----------
    // Thread tid owns obj elements at local float idx 5*tid+4 and 5*tid+1284:
    // lane word-stride 5 (odd) -> conflict-free LDS.
    float acc = 0.0f;
    int ph0 = 0, ph1 = 0;
    for (int i = 0;; i++) {
        long long tile = blockIdx.x + (long long)i * BLOCKS;
        if (tile >= NTILES) break;
        int st = i & 1;
        if (st) { WAITP(mb1, ph1); ph1 ^= 1; }
        else    { WAITP(mb0, ph0); ph0 ^= 1; }

        const float* tp = reinterpret_cast<const float*>(smem_raw + st * TILE_B);
        float x0 = tp[5 * tid + 4];
        float x1 = tp[5 * tid + 1284];   // 5*(tid+256)+4

        acc += fmaxf(x0, 0.0f) + fmaxf(x1, 0.0f);
        float e0 = __expf(-fabsf(x0));
        float e1 = __expf(-fabsf(x1));
        acc += logf((1.0f + e0) * (1.0f + e1));   // terms in [1,2], product <= 4

        __syncthreads();   // all threads done reading buffer st
        long long nt = tile + 2LL * BLOCKS;
        if (nt < NTILES && tid == 0) {
            unsigned mb = st ? mb1 : mb0;
            MBAR_EXPECT(mb, TILE_B);
            BULK_G2S_EL(sb + st * TILE_B, pb + nt * TILE_B, TILE_B, mb, pol);
        }
    }

    s_red[tid] = acc;
    __syncthreads();
    #pragma unroll
    for (int o = THREADS / 2; o > 0; o >>= 1) {
        if (tid < o) s_red[tid] += s_red[tid + o];
        __syncthreads();
    }

    if (tid == 0) {
        g_partials[blockIdx.x] = s_red[0];
        __threadfence();   // orders partials AND (for PREP_BLOCK) g_box3/g_npos
        int old = atomicAdd(&g_counter, 1);
        is_last = (old == (int)gridDim.x - 1);
    }
    __syncthreads();
    if (!is_last) return;

    // ---------- Tail: last block only — reduce partials, combine, output ----------
    float sall = 0.0f;
    for (int i = tid; i < BLOCKS; i += THREADS) sall += g_partials[i];
    s_red[tid] = sall;
    __syncthreads();
    #pragma unroll
    for (int o = THREADS / 2; o > 0; o >>= 1) {
        if (tid < o) s_red[tid] += s_red[tid + o];
        __syncthreads();
    }

    if (tid == 0) {
        float np = (float)g_npos;
        float nn = (float)NCELL - np;
        float c  = 5.0f * g_box3[0] / fmaxf(np, 1.0f);
        float ob = 1.0f * g_box3[1] / fmaxf(np, 1.0f);
        float no = 0.5f * (s_red[0] - g_box3[2]) / fmaxf(nn, 1.0f);
        out[0] = c + ob + no;
        out[1] = c;
        out[2] = ob;
        out[3] = no;
        out[4] = 0.0f;
        g_counter = 0;   // reset for next graph replay (deterministic)
    }
}

extern "C" void kernel_launch(void* const* d_in, const int* in_sizes, int n_in,
                              void* d_out, int out_size) {
    const float* pred = (const float*)d_in[0];
    const float* bbox = (const float*)d_in[1];
    float* out = (float*)d_out;
    (void)in_sizes; (void)n_in; (void)out_size;

    loss_kernel<<<BLOCKS, THREADS>>>(pred, bbox, out);
}

// round 16
// speedup vs baseline: 1.1233x; 1.1233x over previous
#include <cuda_runtime.h>
#include <math.h>

// Fixed shapes per reference
#define HH    112
#define WW    112
#define AA    9
#define NBOX  768          // B * 24
#define NCELL 3612672      // B*H*W*A

#define TILE_B   10240     // bytes per bulk-copy tile (2560 floats, mult of 5)
#define NTILES   7056      // 72,253,440 / 10,240
#define BLOCKS   1216      // 8 CTAs x 152 SMs
#define THREADS  256
// Contiguous partition: first REM blocks own (BASE+1) tiles, rest own BASE.
#define BASE     5         // 7056 / 1216
#define REM      976       // 7056 - 5*1216
#define PREP_BLOCK 1215    // in the 5-tile group: has slack for box prep

__device__ float g_partials[BLOCKS];
__device__ int   g_counter = 0;   // zero-inited; last block resets it
__device__ float g_box3[3];       // coord, objs, sppos (written by PREP_BLOCK)
__device__ int   g_npos;

__device__ __forceinline__ float softplus_acc(float x) {
    return fmaxf(x, 0.0f) + log1pf(expf(-fabsf(x)));
}

__device__ __forceinline__ unsigned smem_u32(const void* p) {
    return (unsigned)__cvta_generic_to_shared(p);
}

#define MBAR_INIT(a, c) \
    asm volatile("mbarrier.init.shared.b64 [%0], %1;" :: "r"(a), "r"(c) : "memory")
#define MBAR_EXPECT(a, b) \
    asm volatile("mbarrier.arrive.expect_tx.shared.b64 _, [%0], %1;" :: "r"(a), "r"(b) : "memory")
#define BULK_G2S(dst, src, n, mb) \
    asm volatile("cp.async.bulk.shared::cta.global.mbarrier::complete_tx::bytes [%0], [%1], %2, [%3];" \
                 :: "r"(dst), "l"(src), "r"(n), "r"(mb) : "memory")
#define WAITP(mb, ph) do { \
    asm volatile("{\n\t.reg .pred P;\n" \
                 "W%=:\n\tmbarrier.try_wait.parity.acquire.cta.shared::cta.b64 P, [%0], %1;\n" \
                 "\t@P bra D%=;\n\tbra W%=;\nD%=:\n\t}" \
                 :: "r"(mb), "r"(ph) : "memory"); \
} while (0)

__global__ __launch_bounds__(THREADS, 8) void loss_kernel(const float* __restrict__ pred,
                                                          const float* __restrict__ bbox,
                                                          float* __restrict__ out) {
    __shared__ __align__(128) unsigned char smem_raw[2 * TILE_B];
    __shared__ __align__(8) unsigned long long mbar[2];
    __shared__ float s_red[THREADS];
    __shared__ int   s_key[NBOX];     // used only by PREP_BLOCK
    __shared__ bool  is_last;

    const int tid = threadIdx.x;
    const unsigned sb  = smem_u32(smem_raw);
    const unsigned mb0 = smem_u32(&mbar[0]);
    const unsigned mb1 = smem_u32(&mbar[1]);
    const char* __restrict__ pb = reinterpret_cast<const char*>(pred);

    // Contiguous tile range for this CTA
    const int bid = blockIdx.x;
    const long long t_begin = (bid < REM) ? (long long)bid * (BASE + 1)
                                          : (long long)REM * (BASE + 1) + (long long)(bid - REM) * BASE;
    const int n_my = (bid < REM) ? (BASE + 1) : BASE;

    if (tid == 0) { MBAR_INIT(mb0, 1); MBAR_INIT(mb1, 1); }
    __syncthreads();

    // Kick off the first two bulk copies immediately (overlap with prep below).
    if (tid == 0) {
        MBAR_EXPECT(mb0, TILE_B);
        BULK_G2S(sb, pb + t_begin * TILE_B, TILE_B, mb0);
        if (n_my > 1) {
            MBAR_EXPECT(mb1, TILE_B);
            BULK_G2S(sb + TILE_B, pb + (t_begin + 1) * TILE_B, TILE_B, mb1);
        }
    }

    // ---------- Box prep: PREP_BLOCK only, overlapped with its streaming slack ----------
    if (bid == PREP_BLOCK) {
        float aw[AA], ah[AA];
        {
            const double S[3] = {32.0, 64.0, 128.0};
            const double R[3] = {0.5, 1.0, 2.0};
            #pragma unroll
            for (int i = 0; i < AA; i++) {
                double sd = S[i / 3], rd = R[i % 3];
                aw[i] = (float)(sd * sqrt(rd) / 224.0);
                ah[i] = (float)(sd / sqrt(rd) / 224.0);
            }
        }

        float tgt[3][4];
        #pragma unroll
        for (int k = 0; k < 3; k++) {
            int idx = tid + k * THREADS;
            float cx = bbox[idx * 4 + 0];
            float cy = bbox[idx * 4 + 1];
            float w  = bbox[idx * 4 + 2];
            float h  = bbox[idx * 4 + 3];
            bool valid = (cx != 0.0f) || (cy != 0.0f) || (w != 0.0f) || (h != 0.0f);
            if (!valid) { s_key[idx] = -1; tgt[k][0]=tgt[k][1]=tgt[k][2]=tgt[k][3]=0.0f; continue; }

            int gx = (int)floorf(cx * (float)WW); gx = min(max(gx, 0), WW - 1);
            int gy = (int)floorf(cy * (float)HH); gy = min(max(gy, 0), HH - 1);

            float wh = w * h;
            int best = 0; float bi = -1e30f;
            #pragma unroll
            for (int a = 0; a < AA; a++) {
                float inter = fminf(w, aw[a]) * fminf(h, ah[a]);
                float uni   = wh + aw[a] * ah[a] - inter;
                float iou   = inter / (uni + 1e-16f);
                if (iou > bi) { bi = iou; best = a; }   // first max wins (strict >)
            }

            int b = idx / 24;
            s_key[idx] = ((b * HH + gy) * WW + gx) * AA + best;
            tgt[k][0] = cx * (float)WW - (float)gx;
            tgt[k][1] = cy * (float)HH - (float)gy;
            tgt[k][2] = logf(w / aw[best] + 1e-16f);
            tgt[k][3] = logf(h / ah[best] + 1e-16f);
        }
        __syncthreads();

        float coord = 0.0f, objs = 0.0f, sppos = 0.0f;
        int npos = 0;
        #pragma unroll
        for (int k = 0; k < 3; k++) {
            int idx = tid + k * THREADS;
            int key = s_key[idx];
            if (key < 0) continue;
            int bend = ((idx / 24) + 1) * 24;
            bool win = true;
            for (int j = idx + 1; j < bend; j++) {
                if (s_key[j] == key) { win = false; break; }
            }
            if (!win) continue;

            const float* p = pred + (long long)key * 5;
            float d0 = p[0] - tgt[k][0];
            float d1 = p[1] - tgt[k][1];
            float d2 = p[2] - tgt[k][2];
            float d3 = p[3] - tgt[k][3];
            coord += d0 * d0 + d1 * d1 + d2 * d2 + d3 * d3;
            float o = p[4];
            objs  += softplus_acc(-o);
            sppos += softplus_acc(o);
            npos++;
        }

        float vals[3] = {coord, objs, sppos};
        #pragma unroll
        for (int v = 0; v < 3; v++) {
            s_red[tid] = vals[v];
            __syncthreads();
            #pragma unroll
            for (int o = THREADS / 2; o > 0; o >>= 1) {
                if (tid < o) s_red[tid] += s_red[tid + o];
                __syncthreads();
            }
            if (tid == 0) g_box3[v] = s_red[0];
            __syncthreads();
        }
        s_red[tid] = (float)npos;
        __syncthreads();
        #pragma unroll
        for (int o = THREADS / 2; o > 0; o >>= 1) {
            if (tid < o) s_red[tid] += s_red[tid + o];
            __syncthreads();
        }
        if (tid == 0) g_npos = (int)s_red[0];
        __syncthreads();
    }

    // ---------- Phase 1: bulk-copy pipeline over contiguous tile range ----------
    // Thread tid owns obj elements at local float idx 5*tid+4 and 5*tid+1284:
    // lane word-stride 5 (odd) -> conflict-free LDS.
    float acc = 0.0f;
    int ph0 = 0, ph1 = 0;
    for (int i = 0; i < n_my; i++) {
        int st = i & 1;
        if (st) { WAITP(mb1, ph1); ph1 ^= 1; }
        else    { WAITP(mb0, ph0); ph0 ^= 1; }

        const float* tp = reinterpret_cast<const float*>(smem_raw + st * TILE_B);
        float x0 = tp[5 * tid + 4];
        float x1 = tp[5 * tid + 1284];   // 5*(tid+256)+4

        acc += fmaxf(x0, 0.0f) + fmaxf(x1, 0.0f);
        float e0 = __expf(-fabsf(x0));
        float e1 = __expf(-fabsf(x1));
        acc += logf((1.0f + e0) * (1.0f + e1));   // terms in [1,2], product <= 4

        __syncthreads();   // all threads done reading buffer st
        if (i + 2 < n_my && tid == 0) {
            unsigned mb = st ? mb1 : mb0;
            MBAR_EXPECT(mb, TILE_B);
            BULK_G2S(sb + st * TILE_B, pb + (t_begin + i + 2) * TILE_B, TILE_B, mb);
        }
    }

    s_red[tid] = acc;
    __syncthreads();
    #pragma unroll
    for (int o = THREADS / 2; o > 0; o >>= 1) {
        if (tid < o) s_red[tid] += s_red[tid + o];
        __syncthreads();
    }

    if (tid == 0) {
        g_partials[bid] = s_red[0];
        __threadfence();   // orders partials AND (for PREP_BLOCK) g_box3/g_npos
        int old = atomicAdd(&g_counter, 1);
        is_last = (old == (int)gridDim.x - 1);
    }
    __syncthreads();
    if (!is_last) return;

    // ---------- Tail: last block only — reduce partials, combine, output ----------
    float sall = 0.0f;
    for (int i = tid; i < BLOCKS; i += THREADS) sall += g_partials[i];
    s_red[tid] = sall;
    __syncthreads();
    #pragma unroll
    for (int o = THREADS / 2; o > 0; o >>= 1) {
        if (tid < o) s_red[tid] += s_red[tid + o];
        __syncthreads();
    }

    if (tid == 0) {
        float np = (float)g_npos;
        float nn = (float)NCELL - np;
        float c  = 5.0f * g_box3[0] / fmaxf(np, 1.0f);
        float ob = 1.0f * g_box3[1] / fmaxf(np, 1.0f);
        float no = 0.5f * (s_red[0] - g_box3[2]) / fmaxf(nn, 1.0f);
        out[0] = c + ob + no;
        out[1] = c;
        out[2] = ob;
        out[3] = no;
        out[4] = 0.0f;
        g_counter = 0;   // reset for next graph replay (deterministic)
    }
}

extern "C" void kernel_launch(void* const* d_in, const int* in_sizes, int n_in,
                              void* d_out, int out_size) {
    const float* pred = (const float*)d_in[0];
    const float* bbox = (const float*)d_in[1];
    float* out = (float*)d_out;
    (void)in_sizes; (void)n_in; (void)out_size;

    loss_kernel<<<BLOCKS, THREADS>>>(pred, bbox, out);
}